// round 2
// baseline (speedup 1.0000x reference)
#include <cuda_runtime.h>
#include <math.h>

#define BQ 32     // batch
#define SQ 32     // query tokens
#define HD 128    // hidden
#define CD 512    // docs
#define DD 128    // doc tokens
#define HC 64     // h chunk held in smem
#define INV_TEMP 50.0f   // 1/0.02

// scores[b][c], written by kernel 1, consumed by kernel 2 (no allocations allowed)
__device__ float g_scores[BQ * CD];

// ---------------------------------------------------------------------------
// Kernel 1: one CTA per (b, c). Computes
//   scores[b][c] = (sum_s max_d  dot(Q[b,s,:], P[c,d,:])) / T
// 128 threads, each owns a 4(s) x 8(d) accumulator tile, outer-product over h.
// Smem tiles are stored h-major (transposed) so the per-h fragment loads are
// contiguous; P tile uses an xor swizzle on 4-float blocks to kill the
// transpose-store bank conflicts.
// ---------------------------------------------------------------------------
__global__ __launch_bounds__(128, 5)
void maxsim_kernel(const float* __restrict__ Q, const float* __restrict__ P) {
    const int b = blockIdx.y;
    const int c = blockIdx.x;

    __shared__ __align__(16) float Qs[HC][33];    // [h][s], pad to 33 (2-way stores)
    __shared__ __align__(16) float Ps[HC][128];   // [h][d_swizzled]
    __shared__ float smax[SQ];

    const int tid = threadIdx.x;
    const int dx  = tid & 15;    // 16 thread-columns over d (8 d each)
    const int sy  = tid >> 4;    // 8 thread-rows over s (4 s each)

    float acc[4][8];
#pragma unroll
    for (int i = 0; i < 4; ++i)
#pragma unroll
        for (int j = 0; j < 8; ++j) acc[i][j] = -1e30f * 0.0f;  // 0.0f
#pragma unroll
    for (int i = 0; i < 4; ++i)
#pragma unroll
        for (int j = 0; j < 8; ++j) acc[i][j] = 0.0f;

    const float* Qb = Q + (size_t)b * (SQ * HD);
    const float* Pc = P + (size_t)c * (DD * HD);

    for (int hc = 0; hc < HD; hc += HC) {
        __syncthreads();  // previous chunk fully consumed before overwrite

        // ---- load Q chunk: 32 s x 64 h -> Qs[h][s] (transposed) ----
#pragma unroll
        for (int k = 0; k < 4; ++k) {
            int i   = tid + k * 128;         // 0..511
            int hh4 = i & 15;                // float4 index along h
            int s   = i >> 4;                // 0..31
            float4 v = *reinterpret_cast<const float4*>(Qb + s * HD + hc + hh4 * 4);
            int r = hh4 * 4;
            Qs[r + 0][s] = v.x;
            Qs[r + 1][s] = v.y;
            Qs[r + 2][s] = v.z;
            Qs[r + 3][s] = v.w;
        }

        // ---- load P chunk: 128 d x 64 h -> Ps[h][swz(d)] (transposed+swizzled) ----
#pragma unroll
        for (int k = 0; k < 16; ++k) {
            int i   = tid + k * 128;         // 0..2047
            int hh4 = i & 15;
            int d   = i >> 4;                // 0..127
            float4 v = *reinterpret_cast<const float4*>(Pc + d * HD + hc + hh4 * 4);
            int swz = ((((d >> 2) ^ (hh4 & 7)) << 2) | (d & 3));
            int r = hh4 * 4;
            Ps[r + 0][swz] = v.x;
            Ps[r + 1][swz] = v.y;
            Ps[r + 2][swz] = v.z;
            Ps[r + 3][swz] = v.w;
        }
        __syncthreads();

        // ---- outer-product accumulation over this h chunk ----
#pragma unroll 8
        for (int h = 0; h < HC; ++h) {
            const int cswz = (h >> 2) & 7;
            float a0 = Qs[h][sy * 4 + 0];
            float a1 = Qs[h][sy * 4 + 1];
            float a2 = Qs[h][sy * 4 + 2];
            float a3 = Qs[h][sy * 4 + 3];
            float4 b0 = *reinterpret_cast<const float4*>(&Ps[h][(dx ^ cswz) << 2]);
            float4 b1 = *reinterpret_cast<const float4*>(&Ps[h][((16 + dx) ^ cswz) << 2]);
            float bb[8] = {b0.x, b0.y, b0.z, b0.w, b1.x, b1.y, b1.z, b1.w};
#pragma unroll
            for (int j = 0; j < 8; ++j) {
                acc[0][j] = fmaf(a0, bb[j], acc[0][j]);
                acc[1][j] = fmaf(a1, bb[j], acc[1][j]);
                acc[2][j] = fmaf(a2, bb[j], acc[2][j]);
                acc[3][j] = fmaf(a3, bb[j], acc[3][j]);
            }
        }
    }

    // ---- max over d (thread-local 8, then across the 16 d-threads) ----
    float m[4];
#pragma unroll
    for (int i = 0; i < 4; ++i) {
        float v = acc[i][0];
#pragma unroll
        for (int j = 1; j < 8; ++j) v = fmaxf(v, acc[i][j]);
        m[i] = v;
    }
#pragma unroll
    for (int off = 1; off < 16; off <<= 1) {
#pragma unroll
        for (int i = 0; i < 4; ++i)
            m[i] = fmaxf(m[i], __shfl_xor_sync(0xffffffffu, m[i], off));
    }
    if (dx == 0) {
#pragma unroll
        for (int i = 0; i < 4; ++i) smax[sy * 4 + i] = m[i];
    }
    __syncthreads();

    // ---- sum over s, scale by 1/T ----
    if (tid < 32) {
        float v = smax[tid];
#pragma unroll
        for (int off = 16; off; off >>= 1) v += __shfl_xor_sync(0xffffffffu, v, off);
        if (tid == 0) g_scores[b * CD + c] = v * INV_TEMP;
    }
}

// ---------------------------------------------------------------------------
// Kernel 2: loss = mean_b( logsumexp_c(scores[b,:]) - scores[b,0] )
// 32 warps, one warp per batch row.
// ---------------------------------------------------------------------------
__global__ __launch_bounds__(1024)
void loss_kernel(float* __restrict__ out) {
    const int w    = threadIdx.x >> 5;
    const int lane = threadIdx.x & 31;
    const float* row = g_scores + w * CD;

    float mx = -3.402823e38f;
    for (int c = lane; c < CD; c += 32) mx = fmaxf(mx, row[c]);
#pragma unroll
    for (int off = 16; off; off >>= 1) mx = fmaxf(mx, __shfl_xor_sync(0xffffffffu, mx, off));

    float se = 0.0f;
    for (int c = lane; c < CD; c += 32) se += expf(row[c] - mx);
#pragma unroll
    for (int off = 16; off; off >>= 1) se += __shfl_xor_sync(0xffffffffu, se, off);

    __shared__ float part[32];
    if (lane == 0) part[w] = mx + logf(se) - row[0];
    __syncthreads();

    if (w == 0) {
        float v = part[lane];
#pragma unroll
        for (int off = 16; off; off >>= 1) v += __shfl_xor_sync(0xffffffffu, v, off);
        if (lane == 0) out[0] = v * (1.0f / (float)BQ);
    }
}

extern "C" void kernel_launch(void* const* d_in, const int* in_sizes, int n_in,
                              void* d_out, int out_size) {
    const float* Q = (const float*)d_in[0];
    const float* P = (const float*)d_in[1];
    // defensive: match by size (Q has 32*32*128 = 131072 elements)
    if (n_in >= 2 && in_sizes[0] != BQ * SQ * HD) {
        const float* t = Q; Q = P; P = t;
    }
    float* out = (float*)d_out;

    dim3 grid(CD, BQ);
    maxsim_kernel<<<grid, 128>>>(Q, P);
    loss_kernel<<<1, 1024>>>(out);
}